// round 1
// baseline (speedup 1.0000x reference)
#include <cuda_runtime.h>
#include <math.h>

#define NN   50000
#define EE   800000
#define IN_C 128
#define HID  256
#define EMBD 128
#define RR   4

// ---------------- scratch (device globals; no allocation) ----------------
__device__ int      g_deg[NN];
__device__ float    g_invdeg[NN];
__device__ int      g_cnt4[NN * RR];
__device__ float    g_invcnt4[NN * RR];
__device__ float    g_agg1[(size_t)NN * IN_C];
__device__ float    g_x1[(size_t)NN * HID];
__device__ float    g_agg2[(size_t)NN * HID];
__device__ float    g_xsage[(size_t)NN * HID];
__device__ float    g_h[(size_t)NN * 2 * HID];
__device__ float    g_als[NN * 2];
__device__ float    g_ald[NN * 2];
__device__ unsigned g_mxkey[NN * 2];
__device__ float    g_den[NN * 2];
__device__ float    g_gacc[(size_t)NN * 2 * HID];
__device__ float    g_xgat[(size_t)NN * HID];
__device__ float    g_xt[(size_t)RR * NN * EMBD];
__device__ float    g_aggR[(size_t)NN * RR * EMBD];
__device__ float    g_xrgcn[(size_t)NN * EMBD];

// monotone float<->uint encoding for atomicMax on floats
__device__ __forceinline__ unsigned fenc(float f) {
    unsigned u = __float_as_uint(f);
    return (u & 0x80000000u) ? ~u : (u | 0x80000000u);
}
__device__ __forceinline__ float fdec(unsigned k) {
    unsigned u = (k & 0x80000000u) ? (k ^ 0x80000000u) : ~k;
    return __uint_as_float(u);
}

// ---------------- zero kernels ----------------
__global__ void k_zero_small() {
    int i = blockIdx.x * blockDim.x + threadIdx.x;
    if (i < NN) g_deg[i] = 0;
    if (i < NN * 2) { g_mxkey[i] = 0u; g_den[i] = 0.f; }
    if (i < NN * RR) g_cnt4[i] = 0;
}

__global__ void k_zero_big() {
    size_t tid = (size_t)blockIdx.x * blockDim.x + threadIdx.x;
    size_t stride = (size_t)gridDim.x * blockDim.x;
    float4 z = make_float4(0.f, 0.f, 0.f, 0.f);
    float4* a1 = (float4*)g_agg1;  size_t n1 = (size_t)NN * IN_C / 4;
    float4* a2 = (float4*)g_agg2;  size_t n2 = (size_t)NN * HID / 4;
    float4* a3 = (float4*)g_gacc;  size_t n3 = (size_t)NN * 2 * HID / 4;
    float4* a4 = (float4*)g_aggR;  size_t n4 = (size_t)NN * RR * EMBD / 4;
    for (size_t i = tid; i < n1; i += stride) a1[i] = z;
    for (size_t i = tid; i < n2; i += stride) a2[i] = z;
    for (size_t i = tid; i < n3; i += stride) a3[i] = z;
    for (size_t i = tid; i < n4; i += stride) a4[i] = z;
}

// ---------------- degree / relation counts ----------------
__global__ void k_count(const int* __restrict__ dst, const int* __restrict__ et) {
    int i = blockIdx.x * blockDim.x + threadIdx.x;
    if (i >= EE) return;
    int d = dst[i];
    atomicAdd(&g_deg[d], 1);
    atomicAdd(&g_cnt4[d * RR + et[i]], 1);
}

__global__ void k_inv() {
    int i = blockIdx.x * blockDim.x + threadIdx.x;
    if (i >= NN) return;
    g_invdeg[i] = 1.f / fmaxf((float)g_deg[i], 1.f);
#pragma unroll
    for (int r = 0; r < RR; r++)
        g_invcnt4[i * RR + r] = 1.f / fmaxf((float)g_cnt4[i * RR + r], 1.f);
}

// ---------------- generic SAGE scatter-sum (D4 = feature_dim/4) ----------------
__global__ __launch_bounds__(256) void k_sage_scatter(
    const float* __restrict__ xin, const int* __restrict__ src,
    const int* __restrict__ dst, float* __restrict__ agg, int D4) {
    int gw = (int)(((size_t)blockIdx.x * blockDim.x + threadIdx.x) >> 5);
    int lane = threadIdx.x & 31;
    if (gw >= EE) return;
    int s = src[gw], d = dst[gw];
    const float4* xi = (const float4*)xin + (size_t)s * D4;
    float* ag = agg + (size_t)d * D4 * 4;
    for (int j = lane; j < D4; j += 32) {
        float4 v = xi[j];
        atomicAdd(ag + 4 * j + 0, v.x);
        atomicAdd(ag + 4 * j + 1, v.y);
        atomicAdd(ag + 4 * j + 2, v.z);
        atomicAdd(ag + 4 * j + 3, v.w);
    }
}

// ---------------- classic 128x128x8 SGEMM, 8x8 microtile ----------------
// C[M,Nc] = (acc? C:0) + (rowscale? diag(rs):(I)) * A[M,K] @ B[K,Nc] (+bias) (relu?)
__global__ __launch_bounds__(256) void sgemm(
    const float* __restrict__ A, const float* __restrict__ B, float* __restrict__ C,
    const float* __restrict__ rowscale, const float* __restrict__ bias,
    int M, int Nc, int K, int accFlag, int reluFlag) {
    __shared__ float As[8][128];
    __shared__ float Bs[8][128];
    int tid = threadIdx.x;
    int m0 = blockIdx.y * 128;
    int n0 = blockIdx.x * 128;

    int aRow = tid >> 1;
    int aCol = (tid & 1) * 4;
    int bRow = tid >> 5;
    int bCol = (tid & 31) * 4;

    bool aValid = (m0 + aRow) < M;
    float rsA = 1.f;
    if (rowscale != nullptr && aValid) rsA = rowscale[m0 + aRow];
    const float* Aptr = A + (size_t)(m0 + aRow) * K + aCol;
    const float* Bptr = B + (size_t)bRow * Nc + n0 + bCol;

    int tx = tid & 15, ty = tid >> 4;
    float acc[8][8];
#pragma unroll
    for (int i = 0; i < 8; i++)
#pragma unroll
        for (int j = 0; j < 8; j++) acc[i][j] = 0.f;

    for (int k0 = 0; k0 < K; k0 += 8) {
        float4 av = aValid ? *(const float4*)(Aptr + k0) : make_float4(0.f, 0.f, 0.f, 0.f);
        float4 bv = *(const float4*)(Bptr + (size_t)k0 * Nc);
        As[aCol + 0][aRow] = av.x * rsA;
        As[aCol + 1][aRow] = av.y * rsA;
        As[aCol + 2][aRow] = av.z * rsA;
        As[aCol + 3][aRow] = av.w * rsA;
        *(float4*)&Bs[bRow][bCol] = bv;
        __syncthreads();
        float ra[8], rb[8];
#pragma unroll
        for (int kk = 0; kk < 8; kk++) {
#pragma unroll
            for (int i = 0; i < 8; i++) ra[i] = As[kk][ty * 8 + i];
#pragma unroll
            for (int j = 0; j < 8; j++) rb[j] = Bs[kk][tx * 8 + j];
#pragma unroll
            for (int i = 0; i < 8; i++)
#pragma unroll
                for (int j = 0; j < 8; j++) acc[i][j] += ra[i] * rb[j];
        }
        __syncthreads();
    }

#pragma unroll
    for (int i = 0; i < 8; i++) {
        int row = m0 + ty * 8 + i;
        if (row >= M) continue;
        float* cp = C + (size_t)row * Nc + n0 + tx * 8;
#pragma unroll
        for (int j4 = 0; j4 < 2; j4++) {
            float* p = cp + j4 * 4;
            float4 old = accFlag ? *(const float4*)p : make_float4(0.f, 0.f, 0.f, 0.f);
            float4 cv;
            cv.x = acc[i][j4 * 4 + 0] + old.x;
            cv.y = acc[i][j4 * 4 + 1] + old.y;
            cv.z = acc[i][j4 * 4 + 2] + old.z;
            cv.w = acc[i][j4 * 4 + 3] + old.w;
            if (bias != nullptr) {
                const float* bp = bias + n0 + tx * 8 + j4 * 4;
                cv.x += bp[0]; cv.y += bp[1]; cv.z += bp[2]; cv.w += bp[3];
            }
            if (reluFlag) {
                cv.x = fmaxf(cv.x, 0.f); cv.y = fmaxf(cv.y, 0.f);
                cv.z = fmaxf(cv.z, 0.f); cv.w = fmaxf(cv.w, 0.f);
            }
            *(float4*)p = cv;
        }
    }
}

// ---------------- GAT ----------------
__global__ __launch_bounds__(256) void k_al(const float* __restrict__ aS,
                                            const float* __restrict__ aD) {
    int gw = (int)(((size_t)blockIdx.x * blockDim.x + threadIdx.x) >> 5);
    int lane = threadIdx.x & 31;
    if (gw >= NN * 2) return;
    int n = gw >> 1, k = gw & 1;
    const float* hp = g_h + (size_t)n * 512 + k * 256;
    const float* as = aS + k * 256;
    const float* ad = aD + k * 256;
    float ss = 0.f, sd = 0.f;
    for (int d2 = lane; d2 < 256; d2 += 32) {
        float hv = hp[d2];
        ss += hv * as[d2];
        sd += hv * ad[d2];
    }
#pragma unroll
    for (int o = 16; o; o >>= 1) {
        ss += __shfl_down_sync(0xffffffffu, ss, o);
        sd += __shfl_down_sync(0xffffffffu, sd, o);
    }
    if (lane == 0) { g_als[gw] = ss; g_ald[gw] = sd; }
}

__device__ __forceinline__ void gat_edge(int idx, const int* src, const int* dst,
                                         int& s, int& d, int& k, float& e) {
    k = idx & 1;
    int id = idx >> 1;
    if (id < EE) { s = src[id]; d = dst[id]; }
    else { s = d = id - EE; }
    float v = g_als[s * 2 + k] + g_ald[d * 2 + k];
    e = v > 0.f ? v : 0.2f * v;
}

__global__ void k_gatmax(const int* __restrict__ src, const int* __restrict__ dst) {
    int i = blockIdx.x * blockDim.x + threadIdx.x;
    if (i >= (EE + NN) * 2) return;
    int s, d, k; float e;
    gat_edge(i, src, dst, s, d, k, e);
    atomicMax(&g_mxkey[d * 2 + k], fenc(e));
}

__global__ void k_gatden(const int* __restrict__ src, const int* __restrict__ dst) {
    int i = blockIdx.x * blockDim.x + threadIdx.x;
    if (i >= (EE + NN) * 2) return;
    int s, d, k; float e;
    gat_edge(i, src, dst, s, d, k, e);
    float m = fdec(g_mxkey[d * 2 + k]);
    atomicAdd(&g_den[d * 2 + k], expf(e - m));
}

__global__ __launch_bounds__(256) void k_gatscatter(const int* __restrict__ src,
                                                    const int* __restrict__ dst) {
    int gw = (int)(((size_t)blockIdx.x * blockDim.x + threadIdx.x) >> 5);
    int lane = threadIdx.x & 31;
    if (gw >= (EE + NN) * 2) return;
    int s, d, k; float e;
    gat_edge(gw, src, dst, s, d, k, e);
    float m = fdec(g_mxkey[d * 2 + k]);
    float alpha = expf(e - m) / fmaxf(g_den[d * 2 + k], 1e-16f);
    const float4* hs = (const float4*)g_h + (size_t)s * 128 + k * 64;
    float* out = g_gacc + (size_t)d * 512 + k * 256;
#pragma unroll
    for (int it = 0; it < 2; it++) {
        int j = lane + it * 32;
        float4 v = hs[j];
        atomicAdd(out + 4 * j + 0, alpha * v.x);
        atomicAdd(out + 4 * j + 1, alpha * v.y);
        atomicAdd(out + 4 * j + 2, alpha * v.z);
        atomicAdd(out + 4 * j + 3, alpha * v.w);
    }
}

__global__ void k_gatfin(const float* __restrict__ b) {
    int i = blockIdx.x * blockDim.x + threadIdx.x;
    if (i >= NN * HID) return;
    int n = i >> 8, d2 = i & 255;
    float v = 0.5f * (g_gacc[(size_t)n * 512 + d2] + g_gacc[(size_t)n * 512 + 256 + d2]) + b[d2];
    g_xgat[i] = fmaxf(v, 0.f);
}

// ---------------- RGCN ----------------
__global__ __launch_bounds__(256) void k_rgcn_scatter(const int* __restrict__ src,
                                                      const int* __restrict__ dst,
                                                      const int* __restrict__ et) {
    int gw = (int)(((size_t)blockIdx.x * blockDim.x + threadIdx.x) >> 5);
    int lane = threadIdx.x & 31;
    if (gw >= EE) return;
    int s = src[gw], d = dst[gw], r = et[gw];
    const float4* xtp = (const float4*)g_xt + ((size_t)r * NN + s) * 32;
    float* out = g_aggR + ((size_t)d * RR + r) * EMBD;
    float4 v = xtp[lane];
    atomicAdd(out + 4 * lane + 0, v.x);
    atomicAdd(out + 4 * lane + 1, v.y);
    atomicAdd(out + 4 * lane + 2, v.z);
    atomicAdd(out + 4 * lane + 3, v.w);
}

__global__ void k_rgcn_mean() {
    int i = blockIdx.x * blockDim.x + threadIdx.x;
    if (i >= NN * EMBD) return;
    int n = i >> 7, e = i & 127;
    float s = 0.f;
#pragma unroll
    for (int r = 0; r < RR; r++)
        s += g_aggR[((size_t)n * RR + r) * EMBD + e] * g_invcnt4[n * RR + r];
    g_xrgcn[i] = s;
}

// ---------------- final L2 normalize ----------------
__global__ void k_norm(float* __restrict__ out) {
    int n = blockIdx.x;
    int t = threadIdx.x;   // 128 threads
    float v = out[(size_t)n * EMBD + t];
    float s = v * v;
#pragma unroll
    for (int o = 16; o; o >>= 1) s += __shfl_down_sync(0xffffffffu, s, o);
    __shared__ float sh[4];
    if ((t & 31) == 0) sh[t >> 5] = s;
    __syncthreads();
    float tot = sh[0] + sh[1] + sh[2] + sh[3];
    float nrm = fmaxf(sqrtf(tot), 1e-12f);
    out[(size_t)n * EMBD + t] = v / nrm;
}

// ---------------- host ----------------
static void launch_gemm(const float* A, const float* B, float* C,
                        const float* rs, const float* bias,
                        int M, int Nc, int K, int acc, int relu) {
    dim3 grid(Nc / 128, (M + 127) / 128);
    sgemm<<<grid, 256>>>(A, B, C, rs, bias, M, Nc, K, acc, relu);
}

extern "C" void kernel_launch(void* const* d_in, const int* in_sizes, int n_in,
                              void* d_out, int out_size) {
    const float* x    = (const float*)d_in[0];
    const int*   ei   = (const int*)d_in[1];
    const int*   et   = (const int*)d_in[2];
    const float* s1Wl = (const float*)d_in[3];
    const float* s1Wr = (const float*)d_in[4];
    const float* s1b  = (const float*)d_in[5];
    const float* s2Wl = (const float*)d_in[6];
    const float* s2Wr = (const float*)d_in[7];
    const float* s2b  = (const float*)d_in[8];
    const float* gatW = (const float*)d_in[9];
    const float* aSrc = (const float*)d_in[10];
    const float* aDst = (const float*)d_in[11];
    const float* gatB = (const float*)d_in[12];
    const float* Wrel = (const float*)d_in[13];
    const float* Wroot= (const float*)d_in[14];
    const float* rgcB = (const float*)d_in[15];
    const float* fW   = (const float*)d_in[16];
    const float* fB   = (const float*)d_in[17];
    float* out = (float*)d_out;

    const int* src = ei;
    const int* dst = ei + EE;

    // device-global scratch addresses
    float *p_agg1, *p_x1, *p_agg2, *p_xsage, *p_h, *p_xgat, *p_xt, *p_xrgcn, *p_invdeg;
    cudaGetSymbolAddress((void**)&p_agg1, g_agg1);
    cudaGetSymbolAddress((void**)&p_x1, g_x1);
    cudaGetSymbolAddress((void**)&p_agg2, g_agg2);
    cudaGetSymbolAddress((void**)&p_xsage, g_xsage);
    cudaGetSymbolAddress((void**)&p_h, g_h);
    cudaGetSymbolAddress((void**)&p_xgat, g_xgat);
    cudaGetSymbolAddress((void**)&p_xt, g_xt);
    cudaGetSymbolAddress((void**)&p_xrgcn, g_xrgcn);
    cudaGetSymbolAddress((void**)&p_invdeg, g_invdeg);

    // zero accumulators
    k_zero_small<<<(NN * RR + 255) / 256, 256>>>();
    k_zero_big<<<2048, 256>>>();

    // degree + per-(node,rel) counts
    k_count<<<(EE + 255) / 256, 256>>>(dst, et);
    k_inv<<<(NN + 255) / 256, 256>>>();

    // ---- SAGE 1 ----
    k_sage_scatter<<<(EE * 32 + 255) / 256, 256>>>(x, src, dst, p_agg1, IN_C / 4);
    launch_gemm(x, s1Wr, p_x1, nullptr, nullptr, NN, HID, IN_C, 0, 0);
    launch_gemm(p_agg1, s1Wl, p_x1, p_invdeg, s1b, NN, HID, IN_C, 1, 1);

    // ---- SAGE 2 ----
    k_sage_scatter<<<(EE * 32 + 255) / 256, 256>>>(p_x1, src, dst, p_agg2, HID / 4);
    launch_gemm(p_x1, s2Wr, p_xsage, nullptr, nullptr, NN, HID, HID, 0, 0);
    launch_gemm(p_agg2, s2Wl, p_xsage, p_invdeg, s2b, NN, HID, HID, 1, 1);

    // ---- GAT ----
    launch_gemm(p_xsage, gatW, p_h, nullptr, nullptr, NN, 2 * HID, HID, 0, 0);
    k_al<<<(NN * 2 * 32 + 255) / 256, 256>>>(aSrc, aDst);
    int gitems = (EE + NN) * 2;
    k_gatmax<<<(gitems + 255) / 256, 256>>>(src, dst);
    k_gatden<<<(gitems + 255) / 256, 256>>>(src, dst);
    k_gatscatter<<<((size_t)gitems * 32 + 255) / 256, 256>>>(src, dst);
    k_gatfin<<<(NN * HID + 255) / 256, 256>>>(gatB);

    // ---- RGCN ----
    for (int r = 0; r < RR; r++)
        launch_gemm(p_xgat, Wrel + (size_t)r * HID * EMBD, p_xt + (size_t)r * NN * EMBD,
                    nullptr, nullptr, NN, EMBD, HID, 0, 0);
    k_rgcn_scatter<<<(EE * 32 + 255) / 256, 256>>>(src, dst, et);
    k_rgcn_mean<<<(NN * EMBD + 255) / 256, 256>>>();
    launch_gemm(p_xgat, Wroot, p_xrgcn, nullptr, rgcB, NN, EMBD, HID, 1, 0);

    // ---- Fusion + normalize ----
    launch_gemm(p_xsage, fW,                 out, nullptr, nullptr, NN, EMBD, HID, 0, 0);
    launch_gemm(p_xgat,  fW + 256 * EMBD,    out, nullptr, nullptr, NN, EMBD, HID, 1, 0);
    launch_gemm(p_xrgcn, fW + 512 * EMBD,    out, nullptr, fB,      NN, EMBD, EMBD, 1, 0);
    k_norm<<<NN, 128>>>(out);
}

// round 2
// speedup vs baseline: 1.5844x; 1.5844x over previous
#include <cuda_runtime.h>
#include <math.h>

#define NN   50000
#define EE   800000
#define IN_C 128
#define HID  256
#define EMBD 128
#define RR   4
#define NBLK ((NN + 255) / 256)   // 196 scan blocks

// ---------------- scratch (device globals; no allocation) ----------------
__device__ int      g_deg[NN];
__device__ float    g_invdeg[NN];
__device__ int      g_cnt4[NN * RR];
__device__ float    g_invcnt4[NN * RR];
__device__ int      g_rowstart[NN];
__device__ int      g_cursor[NN];
__device__ int      g_bsum[256];
__device__ int      g_boff[256];
__device__ int      g_es[EE];       // CSR: src per slot (sorted by dst)
__device__ int      g_etl[EE];      // CSR: edge type per slot
__device__ float    g_agg1[(size_t)NN * IN_C];
__device__ float    g_x1[(size_t)NN * HID];
__device__ float    g_agg2[(size_t)NN * HID];
__device__ float    g_xsage[(size_t)NN * HID];
__device__ float    g_h[(size_t)NN * 2 * HID];
__device__ float    g_als[NN * 2];
__device__ float    g_ald[NN * 2];
__device__ float    g_xgat[(size_t)NN * HID];
__device__ float    g_xt[(size_t)RR * NN * EMBD];
__device__ float    g_xrgcn[(size_t)NN * EMBD];

__device__ __forceinline__ float lrelu(float v) { return v > 0.f ? v : 0.2f * v; }

// ---------------- zero / counts ----------------
__global__ void k_zero_small() {
    int i = blockIdx.x * blockDim.x + threadIdx.x;
    if (i < NN) { g_deg[i] = 0; g_cursor[i] = 0; }
    if (i < NN * RR) g_cnt4[i] = 0;
}

__global__ void k_count(const int* __restrict__ dst, const int* __restrict__ et) {
    int i = blockIdx.x * blockDim.x + threadIdx.x;
    if (i >= EE) return;
    int d = dst[i];
    atomicAdd(&g_deg[d], 1);
    atomicAdd(&g_cnt4[d * RR + et[i]], 1);
}

__global__ void k_inv() {
    int i = blockIdx.x * blockDim.x + threadIdx.x;
    if (i >= NN) return;
    g_invdeg[i] = 1.f / fmaxf((float)g_deg[i], 1.f);
#pragma unroll
    for (int r = 0; r < RR; r++)
        g_invcnt4[i * RR + r] = 1.f / fmaxf((float)g_cnt4[i * RR + r], 1.f);
}

// ---------------- 3-kernel exclusive scan of g_deg -> g_rowstart ----------------
__global__ void k_scan1() {
    __shared__ int sh[256];
    int b = blockIdx.x, t = threadIdx.x;
    int i = b * 256 + t;
    int v = (i < NN) ? g_deg[i] : 0;
    sh[t] = v; __syncthreads();
    for (int o = 1; o < 256; o <<= 1) {
        int add = (t >= o) ? sh[t - o] : 0;
        __syncthreads();
        sh[t] += add;
        __syncthreads();
    }
    if (i < NN) g_rowstart[i] = sh[t] - v;
    if (t == 255) g_bsum[b] = sh[255];
}

__global__ void k_scan2() {
    __shared__ int sh[256];
    int t = threadIdx.x;
    int v = (t < NBLK) ? g_bsum[t] : 0;
    sh[t] = v; __syncthreads();
    for (int o = 1; o < 256; o <<= 1) {
        int add = (t >= o) ? sh[t - o] : 0;
        __syncthreads();
        sh[t] += add;
        __syncthreads();
    }
    g_boff[t] = sh[t] - v;
}

__global__ void k_scan3() {
    int i = blockIdx.x * blockDim.x + threadIdx.x;
    if (i < NN) g_rowstart[i] += g_boff[i >> 8];
}

__global__ void k_fill(const int* __restrict__ src, const int* __restrict__ dst,
                       const int* __restrict__ et) {
    int e = blockIdx.x * blockDim.x + threadIdx.x;
    if (e >= EE) return;
    int d = dst[e];
    int pos = atomicAdd(&g_cursor[d], 1);
    int slot = g_rowstart[d] + pos;
    g_es[slot] = src[e];
    g_etl[slot] = et[e];
}

// ---------------- SAGE mean-gather: one block per node, one thread per column ----------------
template <int D>
__global__ __launch_bounds__(D) void k_sage_gather(const float* __restrict__ xin,
                                                   float* __restrict__ agg) {
    int n = blockIdx.x;
    int c = threadIdx.x;
    int base = g_rowstart[n], deg = g_deg[n];
    const int* es = g_es + base;
    float acc = 0.f;
    int j = 0;
    for (; j + 4 <= deg; j += 4) {
        int s0 = es[j], s1 = es[j + 1], s2 = es[j + 2], s3 = es[j + 3];
        float v0 = xin[(size_t)s0 * D + c];
        float v1 = xin[(size_t)s1 * D + c];
        float v2 = xin[(size_t)s2 * D + c];
        float v3 = xin[(size_t)s3 * D + c];
        acc += (v0 + v1) + (v2 + v3);
    }
    for (; j < deg; j++) acc += xin[(size_t)es[j] * D + c];
    agg[(size_t)n * D + c] = acc * g_invdeg[n];
}

// ---------------- classic 128x128x8 SGEMM, 8x8 microtile ----------------
__global__ __launch_bounds__(256) void sgemm(
    const float* __restrict__ A, const float* __restrict__ B, float* __restrict__ C,
    const float* __restrict__ bias,
    int M, int Nc, int K, int accFlag, int reluFlag) {
    __shared__ float As[8][128];
    __shared__ float Bs[8][128];
    int tid = threadIdx.x;
    int m0 = blockIdx.y * 128;
    int n0 = blockIdx.x * 128;

    int aRow = tid >> 1;
    int aCol = (tid & 1) * 4;
    int bRow = tid >> 5;
    int bCol = (tid & 31) * 4;

    bool aValid = (m0 + aRow) < M;
    const float* Aptr = A + (size_t)(m0 + aRow) * K + aCol;
    const float* Bptr = B + (size_t)bRow * Nc + n0 + bCol;

    int tx = tid & 15, ty = tid >> 4;
    float acc[8][8];
#pragma unroll
    for (int i = 0; i < 8; i++)
#pragma unroll
        for (int j = 0; j < 8; j++) acc[i][j] = 0.f;

    for (int k0 = 0; k0 < K; k0 += 8) {
        float4 av = aValid ? *(const float4*)(Aptr + k0) : make_float4(0.f, 0.f, 0.f, 0.f);
        float4 bv = *(const float4*)(Bptr + (size_t)k0 * Nc);
        As[aCol + 0][aRow] = av.x;
        As[aCol + 1][aRow] = av.y;
        As[aCol + 2][aRow] = av.z;
        As[aCol + 3][aRow] = av.w;
        *(float4*)&Bs[bRow][bCol] = bv;
        __syncthreads();
        float ra[8], rb[8];
#pragma unroll
        for (int kk = 0; kk < 8; kk++) {
#pragma unroll
            for (int i = 0; i < 8; i++) ra[i] = As[kk][ty * 8 + i];
#pragma unroll
            for (int j = 0; j < 8; j++) rb[j] = Bs[kk][tx * 8 + j];
#pragma unroll
            for (int i = 0; i < 8; i++)
#pragma unroll
                for (int j = 0; j < 8; j++) acc[i][j] += ra[i] * rb[j];
        }
        __syncthreads();
    }

#pragma unroll
    for (int i = 0; i < 8; i++) {
        int row = m0 + ty * 8 + i;
        if (row >= M) continue;
        float* cp = C + (size_t)row * Nc + n0 + tx * 8;
#pragma unroll
        for (int j4 = 0; j4 < 2; j4++) {
            float* p = cp + j4 * 4;
            float4 old = accFlag ? *(const float4*)p : make_float4(0.f, 0.f, 0.f, 0.f);
            float4 cv;
            cv.x = acc[i][j4 * 4 + 0] + old.x;
            cv.y = acc[i][j4 * 4 + 1] + old.y;
            cv.z = acc[i][j4 * 4 + 2] + old.z;
            cv.w = acc[i][j4 * 4 + 3] + old.w;
            if (bias != nullptr) {
                const float* bp = bias + n0 + tx * 8 + j4 * 4;
                cv.x += bp[0]; cv.y += bp[1]; cv.z += bp[2]; cv.w += bp[3];
            }
            if (reluFlag) {
                cv.x = fmaxf(cv.x, 0.f); cv.y = fmaxf(cv.y, 0.f);
                cv.z = fmaxf(cv.z, 0.f); cv.w = fmaxf(cv.w, 0.f);
            }
            *(float4*)p = cv;
        }
    }
}

// ---------------- GAT: per-node attention logits ----------------
__global__ __launch_bounds__(256) void k_al(const float* __restrict__ aS,
                                            const float* __restrict__ aD) {
    int gw = (int)(((size_t)blockIdx.x * blockDim.x + threadIdx.x) >> 5);
    int lane = threadIdx.x & 31;
    if (gw >= NN * 2) return;
    int n = gw >> 1, k = gw & 1;
    const float* hp = g_h + (size_t)n * 512 + k * 256;
    const float* as = aS + k * 256;
    const float* ad = aD + k * 256;
    float ss = 0.f, sd = 0.f;
    for (int d2 = lane; d2 < 256; d2 += 32) {
        float hv = hp[d2];
        ss += hv * as[d2];
        sd += hv * ad[d2];
    }
#pragma unroll
    for (int o = 16; o; o >>= 1) {
        ss += __shfl_down_sync(0xffffffffu, ss, o);
        sd += __shfl_down_sync(0xffffffffu, sd, o);
    }
    if (lane == 0) { g_als[gw] = ss; g_ald[gw] = sd; }
}

// ---------------- GAT: fused softmax + weighted gather, one block per node ----------------
__global__ __launch_bounds__(256) void k_gat(const float* __restrict__ bias) {
    __shared__ float sAl0[256], sAl1[256];
    __shared__ int   sS[256];
    __shared__ float red[256];
    int n = blockIdx.x;
    int t = threadIdx.x;
    int base = g_rowstart[n], deg = g_deg[n];

    float ald0 = g_ald[2 * n], ald1 = g_ald[2 * n + 1];
    float selfE0 = lrelu(g_als[2 * n] + ald0);
    float selfE1 = lrelu(g_als[2 * n + 1] + ald1);

    // pass A: per-head max over edges + self loop
    float m0 = selfE0, m1 = selfE1;
    for (int j = t; j < deg; j += 256) {
        int s = g_es[base + j];
        m0 = fmaxf(m0, lrelu(g_als[2 * s] + ald0));
        m1 = fmaxf(m1, lrelu(g_als[2 * s + 1] + ald1));
    }
    red[t] = m0; __syncthreads();
    for (int o = 128; o; o >>= 1) { if (t < o) red[t] = fmaxf(red[t], red[t + o]); __syncthreads(); }
    m0 = red[0]; __syncthreads();
    red[t] = m1; __syncthreads();
    for (int o = 128; o; o >>= 1) { if (t < o) red[t] = fmaxf(red[t], red[t + o]); __syncthreads(); }
    m1 = red[0]; __syncthreads();

    // pass B: denominator
    float d0 = (t == 0) ? expf(selfE0 - m0) : 0.f;
    float d1 = (t == 0) ? expf(selfE1 - m1) : 0.f;
    for (int j = t; j < deg; j += 256) {
        int s = g_es[base + j];
        d0 += expf(lrelu(g_als[2 * s] + ald0) - m0);
        d1 += expf(lrelu(g_als[2 * s + 1] + ald1) - m1);
    }
    red[t] = d0; __syncthreads();
    for (int o = 128; o; o >>= 1) { if (t < o) red[t] += red[t + o]; __syncthreads(); }
    d0 = red[0]; __syncthreads();
    red[t] = d1; __syncthreads();
    for (int o = 128; o; o >>= 1) { if (t < o) red[t] += red[t + o]; __syncthreads(); }
    d1 = red[0]; __syncthreads();
    float inv0 = 1.f / fmaxf(d0, 1e-16f);
    float inv1 = 1.f / fmaxf(d1, 1e-16f);

    // pass C: weighted gather (self loop + chunked edge list)
    const float* hn = g_h + (size_t)n * 512;
    float a0 = expf(selfE0 - m0) * inv0 * hn[t];
    float a1 = expf(selfE1 - m1) * inv1 * hn[256 + t];
    for (int c0 = 0; c0 < deg; c0 += 256) {
        int cnt = min(256, deg - c0);
        if (t < cnt) {
            int s = g_es[base + c0 + t];
            sS[t] = s;
            sAl0[t] = expf(lrelu(g_als[2 * s] + ald0) - m0) * inv0;
            sAl1[t] = expf(lrelu(g_als[2 * s + 1] + ald1) - m1) * inv1;
        }
        __syncthreads();
        for (int j = 0; j < cnt; j++) {
            const float* hs = g_h + (size_t)sS[j] * 512;
            a0 += sAl0[j] * hs[t];
            a1 += sAl1[j] * hs[256 + t];
        }
        __syncthreads();
    }
    float v = 0.5f * (a0 + a1) + bias[t];
    g_xgat[(size_t)n * 256 + t] = fmaxf(v, 0.f);
}

// ---------------- RGCN gather: per-relation mean folded into per-edge weight ----------------
__global__ __launch_bounds__(128) void k_rgcn() {
    int n = blockIdx.x;
    int c = threadIdx.x;
    int base = g_rowstart[n], deg = g_deg[n];
    float w0 = g_invcnt4[n * 4 + 0], w1 = g_invcnt4[n * 4 + 1];
    float w2 = g_invcnt4[n * 4 + 2], w3 = g_invcnt4[n * 4 + 3];
    float acc = 0.f;
#pragma unroll 2
    for (int j = 0; j < deg; j++) {
        int s = g_es[base + j];
        int r = g_etl[base + j];
        float w = (r == 0) ? w0 : (r == 1) ? w1 : (r == 2) ? w2 : w3;
        acc += w * g_xt[((size_t)r * NN + s) * EMBD + c];
    }
    g_xrgcn[(size_t)n * EMBD + c] = acc;
}

// ---------------- final L2 normalize ----------------
__global__ void k_norm(float* __restrict__ out) {
    int n = blockIdx.x;
    int t = threadIdx.x;   // 128 threads
    float v = out[(size_t)n * EMBD + t];
    float s = v * v;
#pragma unroll
    for (int o = 16; o; o >>= 1) s += __shfl_down_sync(0xffffffffu, s, o);
    __shared__ float sh[4];
    if ((t & 31) == 0) sh[t >> 5] = s;
    __syncthreads();
    float tot = sh[0] + sh[1] + sh[2] + sh[3];
    float nrm = fmaxf(sqrtf(tot), 1e-12f);
    out[(size_t)n * EMBD + t] = v / nrm;
}

// ---------------- host ----------------
static void launch_gemm(const float* A, const float* B, float* C, const float* bias,
                        int M, int Nc, int K, int acc, int relu) {
    dim3 grid(Nc / 128, (M + 127) / 128);
    sgemm<<<grid, 256>>>(A, B, C, bias, M, Nc, K, acc, relu);
}

extern "C" void kernel_launch(void* const* d_in, const int* in_sizes, int n_in,
                              void* d_out, int out_size) {
    const float* x    = (const float*)d_in[0];
    const int*   ei   = (const int*)d_in[1];
    const int*   et   = (const int*)d_in[2];
    const float* s1Wl = (const float*)d_in[3];
    const float* s1Wr = (const float*)d_in[4];
    const float* s1b  = (const float*)d_in[5];
    const float* s2Wl = (const float*)d_in[6];
    const float* s2Wr = (const float*)d_in[7];
    const float* s2b  = (const float*)d_in[8];
    const float* gatW = (const float*)d_in[9];
    const float* aSrc = (const float*)d_in[10];
    const float* aDst = (const float*)d_in[11];
    const float* gatB = (const float*)d_in[12];
    const float* Wrel = (const float*)d_in[13];
    const float* Wroot= (const float*)d_in[14];
    const float* rgcB = (const float*)d_in[15];
    const float* fW   = (const float*)d_in[16];
    const float* fB   = (const float*)d_in[17];
    float* out = (float*)d_out;

    const int* src = ei;
    const int* dst = ei + EE;

    float *p_agg1, *p_x1, *p_agg2, *p_xsage, *p_h, *p_xgat, *p_xt, *p_xrgcn;
    cudaGetSymbolAddress((void**)&p_agg1, g_agg1);
    cudaGetSymbolAddress((void**)&p_x1, g_x1);
    cudaGetSymbolAddress((void**)&p_agg2, g_agg2);
    cudaGetSymbolAddress((void**)&p_xsage, g_xsage);
    cudaGetSymbolAddress((void**)&p_h, g_h);
    cudaGetSymbolAddress((void**)&p_xgat, g_xgat);
    cudaGetSymbolAddress((void**)&p_xt, g_xt);
    cudaGetSymbolAddress((void**)&p_xrgcn, g_xrgcn);

    // ---- CSR build ----
    k_zero_small<<<(NN * RR + 255) / 256, 256>>>();
    k_count<<<(EE + 255) / 256, 256>>>(dst, et);
    k_inv<<<(NN + 255) / 256, 256>>>();
    k_scan1<<<NBLK, 256>>>();
    k_scan2<<<1, 256>>>();
    k_scan3<<<NBLK, 256>>>();
    k_fill<<<(EE + 255) / 256, 256>>>(src, dst, et);

    // ---- SAGE 1 ----
    k_sage_gather<IN_C><<<NN, IN_C>>>(x, p_agg1);
    launch_gemm(x, s1Wr, p_x1, nullptr, NN, HID, IN_C, 0, 0);
    launch_gemm(p_agg1, s1Wl, p_x1, s1b, NN, HID, IN_C, 1, 1);

    // ---- SAGE 2 ----
    k_sage_gather<HID><<<NN, HID>>>(p_x1, p_agg2);
    launch_gemm(p_x1, s2Wr, p_xsage, nullptr, NN, HID, HID, 0, 0);
    launch_gemm(p_agg2, s2Wl, p_xsage, s2b, NN, HID, HID, 1, 1);

    // ---- GAT ----
    launch_gemm(p_xsage, gatW, p_h, nullptr, NN, 2 * HID, HID, 0, 0);
    k_al<<<(NN * 2 * 32 + 255) / 256, 256>>>(aSrc, aDst);
    k_gat<<<NN, 256>>>(gatB);

    // ---- RGCN ----
    for (int r = 0; r < RR; r++)
        launch_gemm(p_xgat, Wrel + (size_t)r * HID * EMBD, p_xt + (size_t)r * NN * EMBD,
                    nullptr, NN, EMBD, HID, 0, 0);
    k_rgcn<<<NN, 128>>>();
    launch_gemm(p_xgat, Wroot, p_xrgcn, rgcB, NN, EMBD, HID, 1, 0);

    // ---- Fusion + normalize ----
    launch_gemm(p_xsage, fW,              out, nullptr, NN, EMBD, HID, 0, 0);
    launch_gemm(p_xgat,  fW + 256 * EMBD, out, nullptr, NN, EMBD, HID, 1, 0);
    launch_gemm(p_xrgcn, fW + 512 * EMBD, out, fB,      NN, EMBD, EMBD, 1, 0);
    k_norm<<<NN, 128>>>(out);
}